// round 7
// baseline (speedup 1.0000x reference)
#include <cuda_runtime.h>

typedef unsigned long long u64;

#define BB   512    // batch
#define TW   512    // encoder time
#define TCC  512    // decoder/context time
#define INP  16     // LSTM input width (F+C)
#define HID  64
#define NG   256    // 4*HID gate rows
#define FD   8      // output features (= C)
#define SPB  4      // samples per block
#define HPAD 68     // padded hidden stride
#define NT   512    // threads per block

__device__ __forceinline__ void ffma2(u64 &a, u64 b, u64 c) {
    asm("fma.rn.f32x2 %0, %1, %2, %0;" : "+l"(a) : "l"(b), "l"(c));
}
__device__ __forceinline__ u64 fadd2(u64 a, u64 b) {
    u64 r; asm("add.rn.f32x2 %0, %1, %2;" : "=l"(r) : "l"(a), "l"(b)); return r;
}
__device__ __forceinline__ u64 pack2(float lo, float hi) {
    u64 r; asm("mov.b64 %0, {%1, %2};" : "=l"(r) : "f"(lo), "f"(hi)); return r;
}
__device__ __forceinline__ float hsum2(u64 v) {
    float lo, hi; asm("mov.b64 {%0, %1}, %2;" : "=f"(lo), "=f"(hi) : "l"(v));
    return lo + hi;
}
__device__ __forceinline__ float tanha(float x) {
    float r; asm("tanh.approx.f32 %0, %1;" : "=f"(r) : "f"(x)); return r;
}
__device__ __forceinline__ float sigf(float x) {
    return fmaf(tanha(0.5f * x), 0.5f, 0.5f);
}

__global__ __launch_bounds__(NT, 1) void lstm_ar_kernel(
    const float* __restrict__ x,     const int* __restrict__ lenx_g,
    const float* __restrict__ ctx,   const int* __restrict__ lctx_g,
    const float* __restrict__ Wih0,  const float* __restrict__ Whh0,
    const float* __restrict__ bih0,  const float* __restrict__ bhh0,
    const float* __restrict__ Wih1,  const float* __restrict__ Whh1,
    const float* __restrict__ bih1,  const float* __restrict__ bhh1,
    const float* __restrict__ Wd,    const float* __restrict__ bd,
    float* __restrict__ out)
{
    __shared__ __align__(16) float xbuf[SPB][INP];
    __shared__ __align__(16) float h0sh[SPB][HPAD];
    __shared__ __align__(16) float h1sh[SPB][HPAD];
    __shared__ __align__(16) float g0sh[SPB][NG];   // gates layer 0 (step t)
    __shared__ __align__(16) float g1sh[SPB][NG];   // gates layer 1 (step t-1)
    __shared__ float wdsh[FD * 65];
    __shared__ float bdsh[FD];
    __shared__ float elem[SPB][FD];
    __shared__ int   lens[SPB];
    __shared__ int   ldec[SPB];

    const int tid = threadIdx.x;
    const int s0  = blockIdx.x * SPB;

    // ---- fill invalid output rows with -999 ----
    {
        const float4 m = make_float4(-999.f, -999.f, -999.f, -999.f);
        #pragma unroll
        for (int s = 0; s < SPB; s++) {
            int lc = lctx_g[s0 + s];
            float4* po = (float4*)(out + (size_t)(s0 + s) * TCC * FD);
            for (int i = lc * 2 + tid; i < (TCC * FD) / 4; i += NT) po[i] = m;
        }
    }

    // ---- K-split weight ownership: thread pair (r, kh), partner = lane^1 ----
    const int r  = tid >> 1;     // gate row 0..255
    const int kh = tid & 1;      // K half: 0 -> [0,32), 1 -> [32,64)
    u64 wA[4], wB[16], wC[16], wD[16];
    {
        const ulonglong2* p = (const ulonglong2*)(Wih0 + r * INP + kh * 8);
        #pragma unroll
        for (int q = 0; q < 2; q++) { ulonglong2 v = p[q]; wA[2*q] = v.x; wA[2*q+1] = v.y; }
        p = (const ulonglong2*)(Whh0 + r * HID + kh * 32);
        #pragma unroll
        for (int q = 0; q < 8; q++) { ulonglong2 v = p[q]; wB[2*q] = v.x; wB[2*q+1] = v.y; }
        p = (const ulonglong2*)(Wih1 + r * HID + kh * 32);
        #pragma unroll
        for (int q = 0; q < 8; q++) { ulonglong2 v = p[q]; wC[2*q] = v.x; wC[2*q+1] = v.y; }
        p = (const ulonglong2*)(Whh1 + r * HID + kh * 32);
        #pragma unroll
        for (int q = 0; q < 8; q++) { ulonglong2 v = p[q]; wD[2*q] = v.x; wD[2*q+1] = v.y; }
    }
    const float bb0 = (kh == 0) ? (bih0[r] + bhh0[r]) : 0.f;
    const float bb1 = (kh == 0) ? (bih1[r] + bhh1[r]) : 0.f;

    if (tid < SPB) { lens[tid] = lenx_g[s0 + tid]; ldec[tid] = lctx_g[s0 + tid] - 1; }
    for (int i = tid; i < FD * HID; i += NT) wdsh[(i >> 6) * 65 + (i & 63)] = Wd[i];
    if (tid < FD) bdsh[tid] = bd[tid];

    // ---- layer-split combine ownership: lay 0 -> c0/h0, lay 1 -> c1/h1 ----
    const int lay = tid >> 8;
    const int cu  = tid & 255;
    const int cs  = cu >> 6, cj = cu & 63;
    if (lay == 0) h0sh[cs][cj] = 0.f; else h1sh[cs][cj] = 0.f;
    float cst = 0.f;    // this thread's cell state (c0 or c1 for unit (cs,cj))

    __syncthreads();

    const int L0s = lens[0], L1s = lens[1], L2s = lens[2], L3s = lens[3];
    const int D0s = ldec[0], D1s = ldec[1], D2s = ldec[2], D3s = ldec[3];
    const int Tenc = max(max(L0s, L1s), max(L2s, L3s));
    const int Tdec = max(max(D0s, D1s), max(D2s, D3s));
    const int myLe = lens[cs];
    const int myLd = ldec[cs];

    const int ps = tid >> 4, pk = tid & 15;   // x prefetch mapping (tid < 64)
    const int ds = tid >> 3, dk = tid & 7;    // ctx prefetch / projection (tid < 32)

    // ---- encoder prologue: xbuf = x(0); g0(0) = x(0)*Wih0 (h0 = 0) ----
    if (tid < 64) xbuf[ps][pk] = x[((size_t)(s0 + ps) * TW) * INP + pk];
    __syncthreads();
    #pragma unroll 1
    for (int s = 0; s < SPB; s++) {
        u64 d0 = pack2(bb0, 0.f), d1 = 0ull;
        const ulonglong2* xp = (const ulonglong2*)(xbuf[s] + kh * 8);
        #pragma unroll
        for (int q = 0; q < 2; q++) { ulonglong2 v = xp[q]; ffma2(d0, wA[2*q], v.x); ffma2(d1, wA[2*q+1], v.y); }
        float g0v = hsum2(fadd2(d0, d1));
        g0v += __shfl_xor_sync(0xFFFFFFFFu, g0v, 1);
        if (kh == 0) g0sh[s][r] = g0v;
    }
    float xn = 0.f;
    if (tid < 64) xn = x[((size_t)(s0 + ps) * TW + min(1, TW - 1)) * INP + pk];
    __syncthreads();

    // ===================== encoder: 2 phases per step =====================
    for (int t = 0; t < Tenc; t++) {
        // ---- combine phase: combine0(t) on lay0 warps, combine1(t-1) on lay1 ----
        if (tid < 64) {
            xbuf[ps][pk] = xn;
            int tt = (t + 2 < TW) ? t + 2 : TW - 1;
            xn = x[((size_t)(s0 + ps) * TW + tt) * INP + pk];
        }
        if (lay == 0) {
            if (t < myLe) {
                float fi = sigf(g0sh[cs][cj]);
                float ff = sigf(g0sh[cs][64 + cj]);
                float fg = tanha(g0sh[cs][128 + cj]);
                float fo = sigf(g0sh[cs][192 + cj]);
                cst = ff * cst + fi * fg;
                h0sh[cs][cj] = fo * tanha(cst);
            }
        } else {
            if (t > 0 && (t - 1) < myLe) {
                float fi = sigf(g1sh[cs][cj]);
                float ff = sigf(g1sh[cs][64 + cj]);
                float fg = tanha(g1sh[cs][128 + cj]);
                float fo = sigf(g1sh[cs][192 + cj]);
                cst = ff * cst + fi * fg;
                h1sh[cs][cj] = fo * tanha(cst);
            }
        }
        __syncthreads();

        // ---- gate phase: g1(t) and g0(t+1), K-split + shfl reduce ----
        #pragma unroll 1
        for (int s = 0; s < SPB; s++) {
            int Ls = (s == 0) ? L0s : (s == 1) ? L1s : (s == 2) ? L2s : L3s;
            if (t < Ls) {
                u64 e0 = pack2(bb1, 0.f), e1 = 0ull;   // g1
                u64 d0 = pack2(bb0, 0.f), d1 = 0ull;   // g0 (next step)
                const ulonglong2* xp = (const ulonglong2*)(xbuf[s] + kh * 8);
                #pragma unroll
                for (int q = 0; q < 2; q++) { ulonglong2 v = xp[q]; ffma2(d0, wA[2*q], v.x); ffma2(d1, wA[2*q+1], v.y); }
                const ulonglong2* h0p = (const ulonglong2*)(h0sh[s] + kh * 32);
                const ulonglong2* h1p = (const ulonglong2*)(h1sh[s] + kh * 32);
                #pragma unroll
                for (int q = 0; q < 8; q++) {
                    ulonglong2 hv = h0p[q];
                    ulonglong2 gv = h1p[q];
                    ffma2(e0, wC[2*q], hv.x);  ffma2(e1, wC[2*q+1], hv.y);
                    ffma2(d0, wB[2*q], hv.x);  ffma2(d1, wB[2*q+1], hv.y);
                    ffma2(e0, wD[2*q], gv.x);  ffma2(e1, wD[2*q+1], gv.y);
                }
                float g1v = hsum2(fadd2(e0, e1));
                float g0v = hsum2(fadd2(d0, d1));
                g1v += __shfl_xor_sync(0xFFFFFFFFu, g1v, 1);
                g0v += __shfl_xor_sync(0xFFFFFFFFu, g0v, 1);
                if (kh == 0) g1sh[s][r] = g1v;
                else if (t + 1 < Ls) g0sh[s][r] = g0v;
            }
        }
        __syncthreads();
    }

    // encoder epilogue: combine1 for step Tenc-1
    if (lay == 1 && (Tenc - 1) < myLe) {
        float fi = sigf(g1sh[cs][cj]);
        float ff = sigf(g1sh[cs][64 + cj]);
        float fg = tanha(g1sh[cs][128 + cj]);
        float fo = sigf(g1sh[cs][192 + cj]);
        cst = ff * cst + fi * fg;
        h1sh[cs][cj] = fo * tanha(cst);
    }
    __syncthreads();

    // ===================== element = h1 @ Wd.T + bd =====================
    if (tid < 32) {
        float a0 = bdsh[dk], a1 = 0.f, a2 = 0.f, a3 = 0.f;
        #pragma unroll
        for (int j = 0; j < HID; j += 4) {
            a0 = fmaf(wdsh[dk * 65 + j    ], h1sh[ds][j    ], a0);
            a1 = fmaf(wdsh[dk * 65 + j + 1], h1sh[ds][j + 1], a1);
            a2 = fmaf(wdsh[dk * 65 + j + 2], h1sh[ds][j + 2], a2);
            a3 = fmaf(wdsh[dk * 65 + j + 3], h1sh[ds][j + 3], a3);
        }
        float e = (a0 + a1) + (a2 + a3);
        elem[ds][dk] = e;
        out[(size_t)(s0 + ds) * TCC * FD + dk] = e;
    }
    __syncthreads();

    // ---- decoder prologue ----
    if (tid < 64 && pk < 8) xbuf[ps][pk] = elem[ps][pk];
    if (tid < 32) xbuf[ds][8 + dk] = ctx[((size_t)(s0 + ds) * TCC) * FD + dk];
    __syncthreads();
    #pragma unroll 1
    for (int s = 0; s < SPB; s++) {
        u64 d0 = pack2(bb0, 0.f), d1 = 0ull;
        const ulonglong2* xp = (const ulonglong2*)(xbuf[s] + kh * 8);
        #pragma unroll
        for (int q = 0; q < 2; q++) { ulonglong2 v = xp[q]; ffma2(d0, wA[2*q], v.x); ffma2(d1, wA[2*q+1], v.y); }
        const ulonglong2* h0p = (const ulonglong2*)(h0sh[s] + kh * 32);
        #pragma unroll
        for (int q = 0; q < 8; q++) { ulonglong2 v = h0p[q]; ffma2(d0, wB[2*q], v.x); ffma2(d1, wB[2*q+1], v.y); }
        float g0v = hsum2(fadd2(d0, d1));
        g0v += __shfl_xor_sync(0xFFFFFFFFu, g0v, 1);
        if (kh == 0) g0sh[s][r] = g0v;
    }
    float cn = 0.f;
    if (tid < 32) cn = ctx[((size_t)(s0 + ds) * TCC + min(1, TCC - 1)) * FD + dk];
    __syncthreads();

    // ===================== decoder: 2 phases per step =====================
    for (int t = 0; t < Tdec; t++) {
        // ---- combine phase ----
        if (tid < 32) {
            xbuf[ds][8 + dk] = cn;
            int tt = (t + 2 < TCC) ? t + 2 : TCC - 1;
            cn = ctx[((size_t)(s0 + ds) * TCC + tt) * FD + dk];
        }
        if (lay == 0) {
            if (t < myLd) {
                float fi = sigf(g0sh[cs][cj]);
                float ff = sigf(g0sh[cs][64 + cj]);
                float fg = tanha(g0sh[cs][128 + cj]);
                float fo = sigf(g0sh[cs][192 + cj]);
                cst = ff * cst + fi * fg;
                h0sh[cs][cj] = fo * tanha(cst);
            }
        } else {
            if (t > 0 && (t - 1) < myLd) {
                float fi = sigf(g1sh[cs][cj]);
                float ff = sigf(g1sh[cs][64 + cj]);
                float fg = tanha(g1sh[cs][128 + cj]);
                float fo = sigf(g1sh[cs][192 + cj]);
                cst = ff * cst + fi * fg;
                h1sh[cs][cj] = fo * tanha(cst);
            }
        }
        __syncthreads();

        // ---- gate phase (+ deferred projection of h1(t-1) -> out row t) ----
        if (tid < 32 && t > 0 && (t - 1) < ldec[ds]) {
            float a0 = bdsh[dk], a1 = 0.f, a2 = 0.f, a3 = 0.f;
            #pragma unroll
            for (int j = 0; j < HID; j += 4) {
                a0 = fmaf(wdsh[dk * 65 + j    ], h1sh[ds][j    ], a0);
                a1 = fmaf(wdsh[dk * 65 + j + 1], h1sh[ds][j + 1], a1);
                a2 = fmaf(wdsh[dk * 65 + j + 2], h1sh[ds][j + 2], a2);
                a3 = fmaf(wdsh[dk * 65 + j + 3], h1sh[ds][j + 3], a3);
            }
            out[((size_t)(s0 + ds) * TCC + t) * FD + dk] = (a0 + a1) + (a2 + a3);
        }
        #pragma unroll 1
        for (int s = 0; s < SPB; s++) {
            int Ds = (s == 0) ? D0s : (s == 1) ? D1s : (s == 2) ? D2s : D3s;
            if (t < Ds) {
                u64 e0 = pack2(bb1, 0.f), e1 = 0ull;
                u64 d0 = pack2(bb0, 0.f), d1 = 0ull;
                const ulonglong2* xp = (const ulonglong2*)(xbuf[s] + kh * 8);
                #pragma unroll
                for (int q = 0; q < 2; q++) { ulonglong2 v = xp[q]; ffma2(d0, wA[2*q], v.x); ffma2(d1, wA[2*q+1], v.y); }
                const ulonglong2* h0p = (const ulonglong2*)(h0sh[s] + kh * 32);
                const ulonglong2* h1p = (const ulonglong2*)(h1sh[s] + kh * 32);
                #pragma unroll
                for (int q = 0; q < 8; q++) {
                    ulonglong2 hv = h0p[q];
                    ulonglong2 gv = h1p[q];
                    ffma2(e0, wC[2*q], hv.x);  ffma2(e1, wC[2*q+1], hv.y);
                    ffma2(d0, wB[2*q], hv.x);  ffma2(d1, wB[2*q+1], hv.y);
                    ffma2(e0, wD[2*q], gv.x);  ffma2(e1, wD[2*q+1], gv.y);
                }
                float g1v = hsum2(fadd2(e0, e1));
                float g0v = hsum2(fadd2(d0, d1));
                g1v += __shfl_xor_sync(0xFFFFFFFFu, g1v, 1);
                g0v += __shfl_xor_sync(0xFFFFFFFFu, g0v, 1);
                if (kh == 0) g1sh[s][r] = g1v;
                else if (t + 1 < Ds) g0sh[s][r] = g0v;
            }
        }
        __syncthreads();
    }

    // decoder epilogue: combine1 for step Tdec-1, then final projection
    if (lay == 1 && (Tdec - 1) < myLd) {
        float fi = sigf(g1sh[cs][cj]);
        float ff = sigf(g1sh[cs][64 + cj]);
        float fg = tanha(g1sh[cs][128 + cj]);
        float fo = sigf(g1sh[cs][192 + cj]);
        cst = ff * cst + fi * fg;
        h1sh[cs][cj] = fo * tanha(cst);
    }
    __syncthreads();
    if (tid < 32 && (Tdec - 1) < ldec[ds]) {
        float a0 = bdsh[dk], a1 = 0.f, a2 = 0.f, a3 = 0.f;
        #pragma unroll
        for (int j = 0; j < HID; j += 4) {
            a0 = fmaf(wdsh[dk * 65 + j    ], h1sh[ds][j    ], a0);
            a1 = fmaf(wdsh[dk * 65 + j + 1], h1sh[ds][j + 1], a1);
            a2 = fmaf(wdsh[dk * 65 + j + 2], h1sh[ds][j + 2], a2);
            a3 = fmaf(wdsh[dk * 65 + j + 3], h1sh[ds][j + 3], a3);
        }
        out[((size_t)(s0 + ds) * TCC + Tdec) * FD + dk] = (a0 + a1) + (a2 + a3);
    }
}

extern "C" void kernel_launch(void* const* d_in, const int* in_sizes, int n_in,
                              void* d_out, int out_size) {
    (void)in_sizes; (void)n_in; (void)out_size;
    lstm_ar_kernel<<<BB / SPB, NT>>>(
        (const float*)d_in[0],  (const int*)d_in[1],
        (const float*)d_in[2],  (const int*)d_in[3],
        (const float*)d_in[4],  (const float*)d_in[5],
        (const float*)d_in[6],  (const float*)d_in[7],
        (const float*)d_in[8],  (const float*)d_in[9],
        (const float*)d_in[10], (const float*)d_in[11],
        (const float*)d_in[12], (const float*)d_in[13],
        (float*)d_out);
}

// round 9
// speedup vs baseline: 3.8400x; 3.8400x over previous
#include <cuda_runtime.h>
#include <cuda_fp16.h>
#include <stdint.h>

#define BB   512
#define TW   512
#define TCC  512
#define INP  16
#define HID  64
#define NG   256
#define FD   8
#define SPB  4
#define NT   512
#define HPAD 68
#define U0S  88     // uf0 stride in halfs (K=80 + pad, bank-conflict-free)
#define U1S  136    // uf1 stride in halfs (K=128 + pad)

__device__ __forceinline__ float tanha(float x) {
    float r; asm("tanh.approx.f32 %0, %1;" : "=f"(r) : "f"(x)); return r;
}
__device__ __forceinline__ float sigf(float x) {
    return fmaf(tanha(0.5f * x), 0.5f, 0.5f);
}
__device__ __forceinline__ uint32_t h2(float a, float b) {
    __half2 h = __floats2half2_rn(a, b);
    return *reinterpret_cast<uint32_t*>(&h);
}
__device__ __forceinline__ void mma16816(
    float &d0, float &d1, float &d2, float &d3,
    uint32_t a0, uint32_t a1, uint32_t a2, uint32_t a3,
    uint32_t b0, uint32_t b1)
{
    asm("mma.sync.aligned.m16n8k16.row.col.f32.f16.f16.f32 "
        "{%0,%1,%2,%3},{%4,%5,%6,%7},{%8,%9},{%0,%1,%2,%3};"
        : "+f"(d0), "+f"(d1), "+f"(d2), "+f"(d3)
        : "r"(a0), "r"(a1), "r"(a2), "r"(a3), "r"(b0), "r"(b1));
}

__global__ __launch_bounds__(NT, 1) void lstm_ar_kernel(
    const float* __restrict__ x,     const int* __restrict__ lenx_g,
    const float* __restrict__ ctx,   const int* __restrict__ lctx_g,
    const float* __restrict__ Wih0,  const float* __restrict__ Whh0,
    const float* __restrict__ bih0,  const float* __restrict__ bhh0,
    const float* __restrict__ Wih1,  const float* __restrict__ Whh1,
    const float* __restrict__ bih1,  const float* __restrict__ bhh1,
    const float* __restrict__ Wd,    const float* __restrict__ bd,
    float* __restrict__ out)
{
    // B operands, n-major: uf0[n][k] = [x(16) | h0(64)] (K=80), uf1 = [h0 | h1] (K=128)
    __shared__ __align__(16) __half uf0[8][U0S];
    __shared__ __align__(16) __half uf1[8][U1S];
    __shared__ __align__(16) float g0sh[SPB][NG];   // layer-0 gates, step t
    __shared__ __align__(16) float g1sh[SPB][NG];   // layer-1 gates, step t-1
    __shared__ __align__(16) float h1sh[SPB][HPAD]; // fp32 h1 for projections
    __shared__ float wdsh[FD * 65];
    __shared__ float bdsh[FD];
    __shared__ float elem[SPB][FD];
    __shared__ int   lens[SPB];
    __shared__ int   ldec[SPB];

    const int tid = threadIdx.x;
    const int s0  = blockIdx.x * SPB;

    // ---- fill invalid output rows with -999 ----
    {
        const float4 m = make_float4(-999.f, -999.f, -999.f, -999.f);
        #pragma unroll
        for (int s = 0; s < SPB; s++) {
            int lc = lctx_g[s0 + s];
            float4* po = (float4*)(out + (size_t)(s0 + s) * TCC * FD);
            for (int i = lc * 2 + tid; i < (TCC * FD) / 4; i += NT) po[i] = m;
        }
    }

    // ---- zero B buffers (samples 4..7 stay zero forever) ----
    {
        __half z = __float2half(0.f);
        __half* p0 = &uf0[0][0];
        for (int i = tid; i < 8 * U0S; i += NT) p0[i] = z;
        __half* p1 = &uf1[0][0];
        for (int i = tid; i < 8 * U1S; i += NT) p1[i] = z;
    }

    // ---- mma identities: warp w owns M-tile w (gate rows R0..R0+15) ----
    const int w    = tid >> 5, lane = tid & 31;
    const int g    = lane >> 2, q = lane & 3;
    const int R0   = w * 16;
    const int rowA = R0 + g, rowB = R0 + g + 8;
    const int c0   = 2 * q;

    // A fragments (fp16 weights in registers)
    uint32_t f0[5][4];   // g0 GEMM: [Wih0 | Whh0], K = 80
    uint32_t f1[8][4];   // g1 GEMM: [Wih1 | Whh1], K = 128
    {
        // kt = 0: Wih0 (16 cols)
        f0[0][0] = h2(Wih0[rowA * INP + c0],     Wih0[rowA * INP + c0 + 1]);
        f0[0][1] = h2(Wih0[rowB * INP + c0],     Wih0[rowB * INP + c0 + 1]);
        f0[0][2] = h2(Wih0[rowA * INP + c0 + 8], Wih0[rowA * INP + c0 + 9]);
        f0[0][3] = h2(Wih0[rowB * INP + c0 + 8], Wih0[rowB * INP + c0 + 9]);
        #pragma unroll
        for (int kt = 1; kt < 5; kt++) {
            int kb = (kt - 1) * 16;
            f0[kt][0] = h2(Whh0[rowA * HID + kb + c0],     Whh0[rowA * HID + kb + c0 + 1]);
            f0[kt][1] = h2(Whh0[rowB * HID + kb + c0],     Whh0[rowB * HID + kb + c0 + 1]);
            f0[kt][2] = h2(Whh0[rowA * HID + kb + c0 + 8], Whh0[rowA * HID + kb + c0 + 9]);
            f0[kt][3] = h2(Whh0[rowB * HID + kb + c0 + 8], Whh0[rowB * HID + kb + c0 + 9]);
        }
        #pragma unroll
        for (int kt = 0; kt < 4; kt++) {
            int kb = kt * 16;
            f1[kt][0] = h2(Wih1[rowA * HID + kb + c0],     Wih1[rowA * HID + kb + c0 + 1]);
            f1[kt][1] = h2(Wih1[rowB * HID + kb + c0],     Wih1[rowB * HID + kb + c0 + 1]);
            f1[kt][2] = h2(Wih1[rowA * HID + kb + c0 + 8], Wih1[rowA * HID + kb + c0 + 9]);
            f1[kt][3] = h2(Wih1[rowB * HID + kb + c0 + 8], Wih1[rowB * HID + kb + c0 + 9]);
        }
        #pragma unroll
        for (int kt = 4; kt < 8; kt++) {
            int kb = (kt - 4) * 16;
            f1[kt][0] = h2(Whh1[rowA * HID + kb + c0],     Whh1[rowA * HID + kb + c0 + 1]);
            f1[kt][1] = h2(Whh1[rowB * HID + kb + c0],     Whh1[rowB * HID + kb + c0 + 1]);
            f1[kt][2] = h2(Whh1[rowA * HID + kb + c0 + 8], Whh1[rowA * HID + kb + c0 + 9]);
            f1[kt][3] = h2(Whh1[rowB * HID + kb + c0 + 8], Whh1[rowB * HID + kb + c0 + 9]);
        }
    }
    const float b0a = bih0[rowA] + bhh0[rowA], b0b = bih0[rowB] + bhh0[rowB];
    const float b1a = bih1[rowA] + bhh1[rowA], b1b = bih1[rowB] + bhh1[rowB];

    if (tid < SPB) { lens[tid] = lenx_g[s0 + tid]; ldec[tid] = lctx_g[s0 + tid] - 1; }
    for (int i = tid; i < FD * HID; i += NT) wdsh[(i >> 6) * 65 + (i & 63)] = Wd[i];
    if (tid < FD) bdsh[tid] = bd[tid];

    // ---- combine ownership: warps 0-7 -> layer0 unit, warps 8-15 -> layer1 ----
    const int lay = tid >> 8;
    const int cu  = tid & 255;
    const int cs  = cu >> 6, cj = cu & 63;
    if (lay == 1) h1sh[cs][cj] = 0.f;
    float cst = 0.f;   // c0 (lay0) or c1 (lay1) for unit (cs, cj)

    __syncthreads();

    const int Tenc = max(max(lens[0], lens[1]), max(lens[2], lens[3]));
    const int Tdec = max(max(ldec[0], ldec[1]), max(ldec[2], ldec[3]));
    const int myLe = lens[cs];
    const int myLd = ldec[cs];

    const int ps = tid >> 4, pk = tid & 15;  // x prefetch (tid < 64)
    const int ds = tid >> 3, dk = tid & 7;   // ctx prefetch / projection (tid < 32)

    // ---- encoder prologue: x(0) -> uf0, g0(0) via mma (h0 = 0) ----
    if (tid < 64) uf0[ps][pk] = __float2half(x[((size_t)(s0 + ps) * TW) * INP + pk]);
    __syncthreads();
    {
        float d0 = b0a, d1 = b0a, d2 = b0b, d3 = b0b;
        #pragma unroll
        for (int kt = 0; kt < 5; kt++) {
            uint32_t bv0 = *reinterpret_cast<const uint32_t*>(&uf0[g][kt * 16 + c0]);
            uint32_t bv1 = *reinterpret_cast<const uint32_t*>(&uf0[g][kt * 16 + c0 + 8]);
            mma16816(d0, d1, d2, d3, f0[kt][0], f0[kt][1], f0[kt][2], f0[kt][3], bv0, bv1);
        }
        if (q < 2) {
            int sA = 2 * q, sB = 2 * q + 1;
            g0sh[sA][rowA] = d0; g0sh[sB][rowA] = d1;
            g0sh[sA][rowB] = d2; g0sh[sB][rowB] = d3;
        }
    }
    float xn = 0.f;
    if (tid < 64) xn = x[((size_t)(s0 + ps) * TW + min(1, TW - 1)) * INP + pk];
    __syncthreads();

    // ===================== encoder =====================
    for (int t = 0; t < Tenc; t++) {
        // ---- combine phase ----
        if (tid < 64) {
            uf0[ps][pk] = __float2half(xn);
            int tt = (t + 2 < TW) ? t + 2 : TW - 1;
            xn = x[((size_t)(s0 + ps) * TW + tt) * INP + pk];
        }
        if (lay == 0) {
            if (t < myLe) {
                float fi = sigf(g0sh[cs][cj]);
                float ff = sigf(g0sh[cs][64 + cj]);
                float fg = tanha(g0sh[cs][128 + cj]);
                float fo = sigf(g0sh[cs][192 + cj]);
                cst = ff * cst + fi * fg;
                float h = fo * tanha(cst);
                __half hf = __float2half(h);
                uf0[cs][16 + cj] = hf;    // h0 for g0 GEMM
                uf1[cs][cj]      = hf;    // h0 for g1 GEMM
            }
        } else {
            if (t > 0 && (t - 1) < myLe) {
                float fi = sigf(g1sh[cs][cj]);
                float ff = sigf(g1sh[cs][64 + cj]);
                float fg = tanha(g1sh[cs][128 + cj]);
                float fo = sigf(g1sh[cs][192 + cj]);
                cst = ff * cst + fi * fg;
                float h = fo * tanha(cst);
                uf1[cs][64 + cj] = __float2half(h);
                h1sh[cs][cj] = h;
            }
        }
        __syncthreads();

        // ---- gate phase: g1(t) and g0(t+1) via tensor cores ----
        {
            float e0 = b1a, e1 = b1a, e2 = b1b, e3 = b1b;
            #pragma unroll
            for (int kt = 0; kt < 8; kt++) {
                uint32_t bv0 = *reinterpret_cast<const uint32_t*>(&uf1[g][kt * 16 + c0]);
                uint32_t bv1 = *reinterpret_cast<const uint32_t*>(&uf1[g][kt * 16 + c0 + 8]);
                mma16816(e0, e1, e2, e3, f1[kt][0], f1[kt][1], f1[kt][2], f1[kt][3], bv0, bv1);
            }
            float d0 = b0a, d1 = b0a, d2 = b0b, d3 = b0b;
            #pragma unroll
            for (int kt = 0; kt < 5; kt++) {
                uint32_t bv0 = *reinterpret_cast<const uint32_t*>(&uf0[g][kt * 16 + c0]);
                uint32_t bv1 = *reinterpret_cast<const uint32_t*>(&uf0[g][kt * 16 + c0 + 8]);
                mma16816(d0, d1, d2, d3, f0[kt][0], f0[kt][1], f0[kt][2], f0[kt][3], bv0, bv1);
            }
            if (q < 2) {
                int sA = 2 * q, sB = 2 * q + 1;
                g1sh[sA][rowA] = e0; g1sh[sB][rowA] = e1;
                g1sh[sA][rowB] = e2; g1sh[sB][rowB] = e3;
                g0sh[sA][rowA] = d0; g0sh[sB][rowA] = d1;
                g0sh[sA][rowB] = d2; g0sh[sB][rowB] = d3;
            }
        }
        __syncthreads();
    }

    // encoder epilogue: combine1 for step Tenc-1
    if (lay == 1 && (Tenc - 1) < myLe) {
        float fi = sigf(g1sh[cs][cj]);
        float ff = sigf(g1sh[cs][64 + cj]);
        float fg = tanha(g1sh[cs][128 + cj]);
        float fo = sigf(g1sh[cs][192 + cj]);
        cst = ff * cst + fi * fg;
        float h = fo * tanha(cst);
        uf1[cs][64 + cj] = __float2half(h);
        h1sh[cs][cj] = h;
    }
    __syncthreads();

    // ===================== element = h1 @ Wd.T + bd =====================
    if (tid < 32) {
        float a0 = bdsh[dk], a1 = 0.f, a2 = 0.f, a3 = 0.f;
        #pragma unroll
        for (int j = 0; j < HID; j += 4) {
            a0 = fmaf(wdsh[dk * 65 + j    ], h1sh[ds][j    ], a0);
            a1 = fmaf(wdsh[dk * 65 + j + 1], h1sh[ds][j + 1], a1);
            a2 = fmaf(wdsh[dk * 65 + j + 2], h1sh[ds][j + 2], a2);
            a3 = fmaf(wdsh[dk * 65 + j + 3], h1sh[ds][j + 3], a3);
        }
        float e = (a0 + a1) + (a2 + a3);
        elem[ds][dk] = e;
        out[(size_t)(s0 + ds) * TCC * FD + dk] = e;
    }
    __syncthreads();

    // ---- decoder prologue: dec input = [elem | ctx(0)]; g0_dec(0) via mma ----
    if (tid < 64 && pk < 8) uf0[ps][pk] = __float2half(elem[ps][pk]);
    if (tid < 32) uf0[ds][8 + dk] = __float2half(ctx[((size_t)(s0 + ds) * TCC) * FD + dk]);
    __syncthreads();
    {
        float d0 = b0a, d1 = b0a, d2 = b0b, d3 = b0b;
        #pragma unroll
        for (int kt = 0; kt < 5; kt++) {
            uint32_t bv0 = *reinterpret_cast<const uint32_t*>(&uf0[g][kt * 16 + c0]);
            uint32_t bv1 = *reinterpret_cast<const uint32_t*>(&uf0[g][kt * 16 + c0 + 8]);
            mma16816(d0, d1, d2, d3, f0[kt][0], f0[kt][1], f0[kt][2], f0[kt][3], bv0, bv1);
        }
        if (q < 2) {
            int sA = 2 * q, sB = 2 * q + 1;
            g0sh[sA][rowA] = d0; g0sh[sB][rowA] = d1;
            g0sh[sA][rowB] = d2; g0sh[sB][rowB] = d3;
        }
    }
    float cn = 0.f;
    if (tid < 32) cn = ctx[((size_t)(s0 + ds) * TCC + min(1, TCC - 1)) * FD + dk];
    __syncthreads();

    // ===================== decoder =====================
    for (int t = 0; t < Tdec; t++) {
        // ---- combine phase ----
        if (tid < 32) {
            uf0[ds][8 + dk] = __float2half(cn);
            int tt = (t + 2 < TCC) ? t + 2 : TCC - 1;
            cn = ctx[((size_t)(s0 + ds) * TCC + tt) * FD + dk];
        }
        if (lay == 0) {
            if (t < myLd) {
                float fi = sigf(g0sh[cs][cj]);
                float ff = sigf(g0sh[cs][64 + cj]);
                float fg = tanha(g0sh[cs][128 + cj]);
                float fo = sigf(g0sh[cs][192 + cj]);
                cst = ff * cst + fi * fg;
                float h = fo * tanha(cst);
                __half hf = __float2half(h);
                uf0[cs][16 + cj] = hf;
                uf1[cs][cj]      = hf;
            }
        } else {
            if (t > 0 && (t - 1) < myLd) {
                float fi = sigf(g1sh[cs][cj]);
                float ff = sigf(g1sh[cs][64 + cj]);
                float fg = tanha(g1sh[cs][128 + cj]);
                float fo = sigf(g1sh[cs][192 + cj]);
                cst = ff * cst + fi * fg;
                float h = fo * tanha(cst);
                uf1[cs][64 + cj] = __float2half(h);
                h1sh[cs][cj] = h;
            }
        }
        __syncthreads();

        // ---- gate phase (+ deferred projection of h1(t-1) -> out row t) ----
        if (tid < 32 && t > 0 && (t - 1) < ldec[ds]) {
            float a0 = bdsh[dk], a1 = 0.f, a2 = 0.f, a3 = 0.f;
            #pragma unroll
            for (int j = 0; j < HID; j += 4) {
                a0 = fmaf(wdsh[dk * 65 + j    ], h1sh[ds][j    ], a0);
                a1 = fmaf(wdsh[dk * 65 + j + 1], h1sh[ds][j + 1], a1);
                a2 = fmaf(wdsh[dk * 65 + j + 2], h1sh[ds][j + 2], a2);
                a3 = fmaf(wdsh[dk * 65 + j + 3], h1sh[ds][j + 3], a3);
            }
            out[((size_t)(s0 + ds) * TCC + t) * FD + dk] = (a0 + a1) + (a2 + a3);
        }
        {
            float e0 = b1a, e1 = b1a, e2 = b1b, e3 = b1b;
            #pragma unroll
            for (int kt = 0; kt < 8; kt++) {
                uint32_t bv0 = *reinterpret_cast<const uint32_t*>(&uf1[g][kt * 16 + c0]);
                uint32_t bv1 = *reinterpret_cast<const uint32_t*>(&uf1[g][kt * 16 + c0 + 8]);
                mma16816(e0, e1, e2, e3, f1[kt][0], f1[kt][1], f1[kt][2], f1[kt][3], bv0, bv1);
            }
            float d0 = b0a, d1 = b0a, d2 = b0b, d3 = b0b;
            #pragma unroll
            for (int kt = 0; kt < 5; kt++) {
                uint32_t bv0 = *reinterpret_cast<const uint32_t*>(&uf0[g][kt * 16 + c0]);
                uint32_t bv1 = *reinterpret_cast<const uint32_t*>(&uf0[g][kt * 16 + c0 + 8]);
                mma16816(d0, d1, d2, d3, f0[kt][0], f0[kt][1], f0[kt][2], f0[kt][3], bv0, bv1);
            }
            if (q < 2) {
                int sA = 2 * q, sB = 2 * q + 1;
                g1sh[sA][rowA] = e0; g1sh[sB][rowA] = e1;
                g1sh[sA][rowB] = e2; g1sh[sB][rowB] = e3;
                g0sh[sA][rowA] = d0; g0sh[sB][rowA] = d1;
                g0sh[sA][rowB] = d2; g0sh[sB][rowB] = d3;
            }
        }
        __syncthreads();
    }

    // decoder epilogue: combine1 for step Tdec-1, then final projection
    if (lay == 1 && (Tdec - 1) < myLd) {
        float fi = sigf(g1sh[cs][cj]);
        float ff = sigf(g1sh[cs][64 + cj]);
        float fg = tanha(g1sh[cs][128 + cj]);
        float fo = sigf(g1sh[cs][192 + cj]);
        cst = ff * cst + fi * fg;
        h1sh[cs][cj] = fo * tanha(cst);
    }
    __syncthreads();
    if (tid < 32 && (Tdec - 1) < ldec[ds]) {
        float a0 = bdsh[dk], a1 = 0.f, a2 = 0.f, a3 = 0.f;
        #pragma unroll
        for (int j = 0; j < HID; j += 4) {
            a0 = fmaf(wdsh[dk * 65 + j    ], h1sh[ds][j    ], a0);
            a1 = fmaf(wdsh[dk * 65 + j + 1], h1sh[ds][j + 1], a1);
            a2 = fmaf(wdsh[dk * 65 + j + 2], h1sh[ds][j + 2], a2);
            a3 = fmaf(wdsh[dk * 65 + j + 3], h1sh[ds][j + 3], a3);
        }
        out[((size_t)(s0 + ds) * TCC + Tdec) * FD + dk] = (a0 + a1) + (a2 + a3);
    }
}

extern "C" void kernel_launch(void* const* d_in, const int* in_sizes, int n_in,
                              void* d_out, int out_size) {
    (void)in_sizes; (void)n_in; (void)out_size;
    lstm_ar_kernel<<<BB / SPB, NT>>>(
        (const float*)d_in[0],  (const int*)d_in[1],
        (const float*)d_in[2],  (const int*)d_in[3],
        (const float*)d_in[4],  (const float*)d_in[5],
        (const float*)d_in[6],  (const float*)d_in[7],
        (const float*)d_in[8],  (const float*)d_in[9],
        (const float*)d_in[10], (const float*)d_in[11],
        (const float*)d_in[12], (const float*)d_in[13],
        (float*)d_out);
}